// round 17
// baseline (speedup 1.0000x reference)
#include <cuda_runtime.h>
#include <cuda_fp16.h>
#include <cstdint>

#define B_     32
#define NPOS   25088
#define NCHUNK 1312     // 32 icb * 41 k16-chunks (koff padded 81->82)
#define NITER  (NCHUNK/4)   // 328 pipeline steps, 4 chunks each

// staged x: [b][icb][ih64][parity2][q32][ic8 x 2B] fp16 -> 65536 B per (b,icb)
__device__ __align__(16) unsigned char g_x[32u * 32u * 65536u];
// packed B fragments (fp16): [chunk][g4][col8][p4][8B] -> 1024 B per chunk
__device__ __align__(16) unsigned char g_wb[(size_t)NCHUNK * 1024u];

// ---------------- fused prep: x -> fp16 staged  |  W -> B fragments ----------------
__global__ void prep(const float* __restrict__ x, const float* __restrict__ W) {
    if (blockIdx.x < 8192) {
        int i = blockIdx.x * 256 + threadIdx.x;          // 2097152 total
        int q = i & 31, r = (i >> 5) & 63, icb = (i >> 11) & 31, b = i >> 16;
        const float* xp = x + (((size_t)b * 256 + icb * 8) * 64 + r) * 64 + 2 * q;
        uint32_t h0[4], h1[4];                           // parity0 (iw=2q), parity1 (iw=2q+1)
        #pragma unroll
        for (int j = 0; j < 4; ++j) {                    // j = ic pair
            uint32_t ha = 0, hb = 0;
            #pragma unroll
            for (int e = 0; e < 2; ++e) {
                float2 v = *reinterpret_cast<const float2*>(xp + (size_t)(2 * j + e) * 4096);
                ha |= (uint32_t)__half_as_ushort(__float2half_rn(v.x)) << (e * 16);
                hb |= (uint32_t)__half_as_ushort(__float2half_rn(v.y)) << (e * 16);
            }
            h0[j] = ha; h1[j] = hb;
        }
        size_t ub = (size_t)(b * 32 + icb) * 65536u + (uint32_t)r * 1024u + (uint32_t)q * 16u;
        *reinterpret_cast<uint4*>(g_x + ub)       = make_uint4(h0[0], h0[1], h0[2], h0[3]);
        *reinterpret_cast<uint4*>(g_x + ub + 512) = make_uint4(h1[0], h1[1], h1[2], h1[3]);
    } else {
        int i = (blockIdx.x - 8192) * 256 + threadIdx.x; // NCHUNK*128 = 167936
        if (i >= NCHUNK * 128) return;
        int p = i & 3, oc = (i >> 2) & 31, c = i >> 7;
        int icb = c / 41, j = c - icb * 41;
        int k0 = 2 * j, k1 = k0 + 1;                     // k1 == 81 -> zero pad
        unsigned short hh[4];
        #pragma unroll
        for (int kk = 0; kk < 2; ++kk) {
            int koff = kk ? k1 : k0;
            #pragma unroll
            for (int e = 0; e < 2; ++e) {
                int ic = icb * 8 + 2 * p + e;
                float v = (koff <= 80) ? W[((size_t)oc * 256 + ic) * 81 + koff] : 0.f;
                hh[kk * 2 + e] = __half_as_ushort(__float2half_rn(v));
            }
        }
        uint2 pk = make_uint2((uint32_t)hh[0] | ((uint32_t)hh[1] << 16),
                              (uint32_t)hh[2] | ((uint32_t)hh[3] << 16));
        size_t off = (size_t)c * 1024 + (oc >> 3) * 256 + (oc & 7) * 32 + p * 8;
        *reinterpret_cast<uint2*>(g_wb + off) = pk;
    }
}

// ---------------- main: fp16 mma, smem B ring, 4 chunks per sync step ----------------
__device__ __forceinline__ void mma_f32(float* c, const uint32_t* a, uint32_t b0, uint32_t b1) {
    asm volatile("mma.sync.aligned.m16n8k16.row.col.f32.f16.f16.f32 "
        "{%0,%1,%2,%3}, {%4,%5,%6,%7}, {%8,%9}, {%0,%1,%2,%3};"
        : "+f"(c[0]), "+f"(c[1]), "+f"(c[2]), "+f"(c[3])
        : "r"(a[0]), "r"(a[1]), "r"(a[2]), "r"(a[3]), "r"(b0), "r"(b1));
}
__device__ __forceinline__ void cpa16s(void* smem, const void* gmem) {
    uint32_t s = (uint32_t)__cvta_generic_to_shared(smem);
    asm volatile("cp.async.ca.shared.global [%0], [%1], 16;" :: "r"(s), "l"(gmem));
}
__device__ __forceinline__ void cpa_commit() { asm volatile("cp.async.commit_group;" ::); }
__device__ __forceinline__ void cpa_wait2()  { asm volatile("cp.async.wait_group 2;" ::); }

__global__ __launch_bounds__(128, 4)
void conv_mma(const float* __restrict__ bias, float* __restrict__ out) {
    __shared__ int s_i0[NCHUNK], s_i1[NCHUNK];
    __shared__ float s_bias[32];
    __shared__ __align__(16) unsigned char s_B[4][4096];   // ring: 4 slots x 4 chunks
    const int tid = threadIdx.x, wid = tid >> 5, lane = tid & 31;

    for (int c = tid; c < NCHUNK; c += 128) {
        int icb = c / 41, j = c - icb * 41;
        int k0 = 2 * j, k1 = (k0 < 80) ? k0 + 1 : 80;   // pad chunk reuses 80's addr (B half = 0)
        int kh0 = k0 / 9, kw0 = k0 - 9 * kh0;
        int kh1 = k1 / 9, kw1 = k1 - 9 * kh1;
        s_i0[c] = icb * 65536 + kh0 * 1024 + (kw0 & 1) * 512 + (kw0 >> 1) * 16;
        s_i1[c] = icb * 65536 + kh1 * 1024 + (kw1 & 1) * 512 + (kw1 >> 1) * 16;
    }
    if (tid < 32) s_bias[tid] = bias[tid];
    __syncthreads();

    // warp-tile: 1568 = 32 b x 49 m16 tiles; pos = tile*16 + row
    const int gidx = blockIdx.x * 4 + wid;
    const int b    = gidx / 49;
    const int tile = gidx - b * 49;
    const int pos_a = tile * 16 + (lane >> 2);
    const int pos_b = pos_a + 8;
    const int oh_a = pos_a / 28, ow_a = pos_a - 28 * oh_a;
    const int oh_b = pos_b / 28, ow_b = pos_b - 28 * oh_b;
    const uint32_t oA = (uint32_t)(oh_a * 2048 + ow_a * 16 + (lane & 3) * 4);
    const uint32_t oB = (uint32_t)(oh_b * 2048 + ow_b * 16 + (lane & 3) * 4);
    const unsigned char* xb = g_x + (size_t)b * (32u * 65536u);
    const uint32_t bfo = (uint32_t)((lane >> 2) * 32 + (lane & 3) * 8);   // B frag offset per g

    float acc[4][4];
    #pragma unroll
    for (int g = 0; g < 4; ++g)
        #pragma unroll
        for (int q = 0; q < 4; ++q) acc[g][q] = 0.f;

    // prologue: slots 0..2 <- chunk quads 0..2 (one group each); A regs for quad 0
    #pragma unroll
    for (int s = 0; s < 3; ++s) {
        cpa16s(&s_B[s][tid * 16],        g_wb + (size_t)s * 4096 + tid * 16);
        cpa16s(&s_B[s][2048 + tid * 16], g_wb + (size_t)s * 4096 + 2048 + tid * 16);
        cpa_commit();
    }
    uint32_t A[4][4];
    #pragma unroll
    for (int cc = 0; cc < 4; ++cc) {
        const int u0 = s_i0[cc], u1 = s_i1[cc];
        A[cc][0] = *(const uint32_t*)(xb + u0 + oA);
        A[cc][1] = *(const uint32_t*)(xb + u0 + oB);
        A[cc][2] = *(const uint32_t*)(xb + u1 + oA);
        A[cc][3] = *(const uint32_t*)(xb + u1 + oB);
    }

    for (int it = 0; it < NITER; ++it) {
        cpa_wait2();          // slot it&3 arrived for this warp
        __syncthreads();      // visible to all; all warps done reading slot (it-1)&3
        const int sn = it + 3;
        if (sn < NITER) {     // refill slot (it+3)&3 = (it-1)&3
            cpa16s(&s_B[sn & 3][tid * 16],        g_wb + (size_t)sn * 4096 + tid * 16);
            cpa16s(&s_B[sn & 3][2048 + tid * 16], g_wb + (size_t)sn * 4096 + 2048 + tid * 16);
        }
        cpa_commit();

        const unsigned char* sp = s_B[it & 3] + bfo;
        const int base = 4 * it + 4;
        #pragma unroll
        for (int cc = 0; cc < 4; ++cc) {
            // compute chunk cc of this slot
            uint2 Bv[4];
            #pragma unroll
            for (int g = 0; g < 4; ++g) Bv[g] = *(const uint2*)(sp + cc * 1024 + g * 256);
            #pragma unroll
            for (int g = 0; g < 4; ++g) mma_f32(acc[g], A[cc], Bv[g].x, Bv[g].y);
            // prefetch A for chunk base+cc (next quad) into the slot just consumed
            const int cn = (base + cc < NCHUNK) ? base + cc : NCHUNK - 1;
            const int u0 = s_i0[cn], u1 = s_i1[cn];
            A[cc][0] = *(const uint32_t*)(xb + u0 + oA);
            A[cc][1] = *(const uint32_t*)(xb + u0 + oB);
            A[cc][2] = *(const uint32_t*)(xb + u1 + oA);
            A[cc][3] = *(const uint32_t*)(xb + u1 + oB);
        }
    }

    // epilogue: bias + squash + T=8 broadcast
    float4* o4 = reinterpret_cast<float4*>(out);
    const size_t ob = (size_t)b * NPOS;
    #pragma unroll
    for (int g = 0; g < 4; ++g) {
        #pragma unroll
        for (int q = 0; q < 4; ++q) {
            const int pos = (q < 2) ? pos_a : pos_b;
            const int oc  = g * 8 + (lane & 3) * 2 + (q & 1);
            float v = acc[g][q] + s_bias[oc];
            float sq = 8.f * v * v;
            float sv = v * (sq / (1.f + sq)) * rsqrtf(sq + 1e-8f);
            float4 f4 = make_float4(sv, sv, sv, sv);
            size_t idx = (ob + (size_t)(oc * 784 + pos)) * 2;
            o4[idx]     = f4;
            o4[idx + 1] = f4;
        }
    }
}

extern "C" void kernel_launch(void* const* d_in, const int* in_sizes, int n_in,
                              void* d_out, int out_size) {
    const float* x    = (const float*)d_in[0];
    const float* W    = (const float*)d_in[1];
    const float* bias = (const float*)d_in[2];
    float* out = (float*)d_out;

    prep<<<8192 + (NCHUNK * 128 + 255) / 256, 256>>>(x, W);   // fused x+W prep
    conv_mma<<<392, 128>>>(bias, out);                        // 392 CTAs = 1568 warp-tiles / 4
}